// round 15
// baseline (speedup 1.0000x reference)
#include <cuda_runtime.h>

#define NN 100000
#define NE 1000000

#define GB ((NN + 63) / 64)               // 1563 tiles
#define GEMM_GRID 444                     // persistent: 3 blocks/SM x 148
#define NODEB_BLOCKS 1480
#define SCANB ((NN + 1023) / 1024)        // 98

#define COMMIT_OFF (NN*64)
#define IDS_OFF (COMMIT_OFF+1)
#define GNN_OFF (IDS_OFF + NN*9)

// ---------------- packed f32x2 helpers ----------------
__device__ __forceinline__ unsigned long long pk2(float lo, float hi) {
    unsigned long long r;
    asm("mov.b64 %0, {%1,%2};" : "=l"(r) : "f"(lo), "f"(hi));
    return r;
}
__device__ __forceinline__ float2 upk2(unsigned long long v) {
    float2 f;
    asm("mov.b64 {%0,%1}, %2;" : "=f"(f.x), "=f"(f.y) : "l"(v));
    return f;
}
__device__ __forceinline__ void fma2(unsigned long long& d,
                                     unsigned long long a, unsigned long long b) {
    asm("fma.rn.f32x2 %0, %1, %2, %0;" : "+l"(d) : "l"(a), "l"(b));
}

// ---------------- scratch (__device__ globals; zero-initialized at load) ----------
// INVARIANT: g_deg, g_fill are zero at the start of every kernel_launch sequence
// (module-load zeros the first run; k_pred re-zeroes them at the end of each run).
__device__ __align__(16) float g_h[NN*64];
__device__ __align__(16) float g_hpre[NN*64];
__device__ __align__(16) float g_xlocal[NN*64];
__device__ __align__(16) float g_Y[NN*64];   // h@Wa
__device__ __align__(16) float g_U[NN*64];   // h@Wr + ba
__device__ __align__(16) float g_S[NN*64];   // h@Wl + bl
__device__ int   g_csr[NE];
__device__ int   g_deg[NN];
__device__ int   g_fill[NN];
__device__ int   g_rowstart[NN];              // local-exclusive
__device__ int   g_rowabs[NN];                // absolute CSR row start
__device__ int   g_bsum[SCANB];
__device__ float g_part[GB * 128];            // per-block BN partials
__device__ float g_cpart[3 * NODEB_BLOCKS];   // per-block commit partials
__device__ float g_bn[128];                   // [0:64) scale, [64:128) shift

// per-warp dtype detect: int64 values < 2^31 have zero hi-words
__device__ __forceinline__ bool warp_is64(const int* ei32, int e) {
    int eC = (e < NE) ? e : NE - 1;
    int hi = ei32[2*eC + 1];
    return __ballot_sync(0xffffffffu, hi != 0) == 0u;
}

// ---------------- degree count ----------------
__global__ void k_prep(const void* __restrict__ eiv) {
    int e = blockIdx.x * blockDim.x + threadIdx.x;
    bool is64 = warp_is64((const int*)eiv, e);
    if (e < NE) {
        int d = is64 ? (int)((const long long*)eiv)[NE + e]
                     : ((const int*)eiv)[NE + e];
        atomicAdd(&g_deg[d], 1);
    }
}

// per-block Hillis-Steele scan of 1024 degrees; local exclusive -> rowstart
__global__ void __launch_bounds__(1024) k_scanA() {
    __shared__ int ss[1024];
    int t = threadIdx.x;
    int node = blockIdx.x * 1024 + t;
    int d = (node < NN) ? g_deg[node] : 0;
    ss[t] = d;
    __syncthreads();
    #pragma unroll
    for (int off = 1; off < 1024; off <<= 1) {
        int v = (t >= off) ? ss[t - off] : 0;
        __syncthreads();
        ss[t] += v;
        __syncthreads();
    }
    if (node < NN) g_rowstart[node] = ss[t] - d;
    if (t == 1023) g_bsum[blockIdx.x] = ss[1023];
}

// helper: redundant in-block scan of the 98 block sums -> sB (inclusive)
__device__ __forceinline__ void scan_bsum(int* sB, int tid) {
    if (tid < 128) sB[tid] = (tid < SCANB) ? g_bsum[tid] : 0;
    __syncthreads();
    #pragma unroll
    for (int off = 1; off < 128; off <<= 1) {
        int v = 0;
        if (tid < 128 && tid >= off) v = sB[tid - off];
        __syncthreads();
        if (tid < 128) sB[tid] += v;
        __syncthreads();
    }
}

// counting-sort edges into CSR + write absolute row starts
__global__ void k_fill(const void* __restrict__ eiv) {
    __shared__ int sB[128];
    int t = threadIdx.x;
    scan_bsum(sB, t);
    int e = blockIdx.x * blockDim.x + t;
    if (e < NN) {
        int blk = e >> 10;
        g_rowabs[e] = g_rowstart[e] + (blk ? sB[blk - 1] : 0);
    }
    bool is64 = warp_is64((const int*)eiv, e);
    if (e < NE) {
        int s, d;
        if (is64) {
            s = (int)((const long long*)eiv)[e];
            d = (int)((const long long*)eiv)[NE + e];
        } else {
            s = ((const int*)eiv)[e];
            d = ((const int*)eiv)[NE + e];
        }
        int blk = d >> 10;
        int pos = g_rowstart[d] + (blk ? sB[blk - 1] : 0) + atomicAdd(&g_fill[d], 1);
        g_csr[pos] = s;
    }
}

// ---------------- persistent dense GEMM: [Y|U|S] = h @ [Wa|Wr|Wl] + [0|ba|bl] ----
// weights loaded ONCE per block; grid-stride over node tiles.
#define SST 66
#define GEMM3_SMEM ((64*SST + 3*4096) * 4)   // 66048 bytes
__global__ void __launch_bounds__(256) k_gemm3(
    const float* __restrict__ x, int layer,
    const float* __restrict__ Wa, const float* __restrict__ Wr,
    const float* __restrict__ Wl,
    const float* __restrict__ ba, const float* __restrict__ bl)
{
    const float* __restrict__ hin = layer ? g_h : x;
    extern __shared__ __align__(16) float dyn[];
    float* sT = dyn;                 // [k][n] stride 66
    float* sW = dyn + 64 * SST;      // Wa | Wr | Wl

    int tid = threadIdx.x;
    int tx = tid & 15, ty = tid >> 4;
    int c0 = tx * 4, n0 = ty * 4;

    // weights once per block
    for (int i = tid; i < 3072; i += 256) {
        const float* src = (i < 1024) ? Wa : (i < 2048) ? Wr : Wl;
        ((float4*)sW)[i] = ((const float4*)src)[i & 1023];
    }
    float4 bu = *(const float4*)(ba + c0);
    float4 bs = *(const float4*)(bl + c0);

    for (int tile = blockIdx.x; tile < GB; tile += GEMM_GRID) {
        int node0 = tile * 64;
        // load input tile transposed
        for (int i = tid; i < 1024; i += 256) {
            int n = i >> 4, kc = i & 15;
            int node = node0 + n;
            float4 hv = make_float4(0.f, 0.f, 0.f, 0.f);
            if (node < NN) hv = *(const float4*)(hin + (size_t)node * 64 + kc * 4);
            int kb = kc * 4;
            sT[(kb+0)*SST+n] = hv.x; sT[(kb+1)*SST+n] = hv.y;
            sT[(kb+2)*SST+n] = hv.z; sT[(kb+3)*SST+n] = hv.w;
        }
        __syncthreads();

        unsigned long long aY[4][2], aU[4][2], aS[4][2];
        #pragma unroll
        for (int i2 = 0; i2 < 4; i2++) {
            aY[i2][0] = pk2(0.f, 0.f);   aY[i2][1] = pk2(0.f, 0.f);
            aU[i2][0] = pk2(bu.x, bu.y); aU[i2][1] = pk2(bu.z, bu.w);
            aS[i2][0] = pk2(bs.x, bs.y); aS[i2][1] = pk2(bs.z, bs.w);
        }

        #pragma unroll 4
        for (int k = 0; k < 64; k++) {
            float2 a01 = *(const float2*)&sT[k*SST + n0];
            float2 a23 = *(const float2*)&sT[k*SST + n0 + 2];
            unsigned long long p0 = pk2(a01.x, a01.x);
            unsigned long long p1 = pk2(a01.y, a01.y);
            unsigned long long p2 = pk2(a23.x, a23.x);
            unsigned long long p3 = pk2(a23.y, a23.y);
            ulonglong2 wa = *(const ulonglong2*)&sW[k*64 + c0];
            ulonglong2 wr = *(const ulonglong2*)&sW[4096 + k*64 + c0];
            ulonglong2 wl = *(const ulonglong2*)&sW[8192 + k*64 + c0];
            fma2(aY[0][0], p0, wa.x); fma2(aY[0][1], p0, wa.y);
            fma2(aY[1][0], p1, wa.x); fma2(aY[1][1], p1, wa.y);
            fma2(aY[2][0], p2, wa.x); fma2(aY[2][1], p2, wa.y);
            fma2(aY[3][0], p3, wa.x); fma2(aY[3][1], p3, wa.y);
            fma2(aU[0][0], p0, wr.x); fma2(aU[0][1], p0, wr.y);
            fma2(aU[1][0], p1, wr.x); fma2(aU[1][1], p1, wr.y);
            fma2(aU[2][0], p2, wr.x); fma2(aU[2][1], p2, wr.y);
            fma2(aU[3][0], p3, wr.x); fma2(aU[3][1], p3, wr.y);
            fma2(aS[0][0], p0, wl.x); fma2(aS[0][1], p0, wl.y);
            fma2(aS[1][0], p1, wl.x); fma2(aS[1][1], p1, wl.y);
            fma2(aS[2][0], p2, wl.x); fma2(aS[2][1], p2, wl.y);
            fma2(aS[3][0], p3, wl.x); fma2(aS[3][1], p3, wl.y);
        }

        #pragma unroll
        for (int i2 = 0; i2 < 4; i2++) {
            int node = node0 + n0 + i2;
            if (node < NN) {
                size_t b = (size_t)node * 64 + c0;
                float2 lo, hi;
                lo = upk2(aY[i2][0]); hi = upk2(aY[i2][1]);
                *(float4*)(g_Y + b) = make_float4(lo.x, lo.y, hi.x, hi.y);
                lo = upk2(aU[i2][0]); hi = upk2(aU[i2][1]);
                *(float4*)(g_U + b) = make_float4(lo.x, lo.y, hi.x, hi.y);
                lo = upk2(aS[i2][0]); hi = upk2(aS[i2][1]);
                *(float4*)(g_S + b) = make_float4(lo.x, lo.y, hi.x, hi.y);
            }
        }
        __syncthreads();   // before next tile overwrites sT
    }
}

// ---------------- gather + l2norm + skip: hpre = l2n(mean(Y[src]) + U) + S -------
// lane handles channels (2*lane, 2*lane+1): 1 LDG.64 per edge row (half the LDGs)
__global__ void __launch_bounds__(256) k_gath2() {
    __shared__ float sRed[8 * 128];
    int tid = threadIdx.x, warp = tid >> 5, lane = tid & 31;

    int node0 = blockIdx.x * 64;
    float cs0 = 0.f, css0 = 0.f, cs1 = 0.f, css1 = 0.f;
    for (int r = warp * 8; r < warp * 8 + 8; r++) {
        int node = node0 + r;
        if (node >= NN) continue;     // warp-uniform
        int beg = g_rowabs[node];
        int dg  = g_deg[node];
        int end = beg + dg;
        float2 a = make_float2(0.f, 0.f), b = a, c = a, d = a;
        int j = beg;
        for (; j + 3 < end; j += 4) {
            float2 v0 = ((const float2*)(g_Y + (size_t)g_csr[j]     * 64))[lane];
            float2 v1 = ((const float2*)(g_Y + (size_t)g_csr[j + 1] * 64))[lane];
            float2 v2 = ((const float2*)(g_Y + (size_t)g_csr[j + 2] * 64))[lane];
            float2 v3 = ((const float2*)(g_Y + (size_t)g_csr[j + 3] * 64))[lane];
            a.x += v0.x; a.y += v0.y;
            b.x += v1.x; b.y += v1.y;
            c.x += v2.x; c.y += v2.y;
            d.x += v3.x; d.y += v3.y;
        }
        for (; j < end; j++) {
            float2 v0 = ((const float2*)(g_Y + (size_t)g_csr[j] * 64))[lane];
            a.x += v0.x; a.y += v0.y;
        }
        float ci = 1.f / (float)(dg > 0 ? dg : 1);
        size_t base = (size_t)node * 64;
        float2 u = ((const float2*)(g_U + base))[lane];
        float t0 = ((a.x + b.x) + (c.x + d.x)) * ci + u.x;
        float t1 = ((a.y + b.y) + (c.y + d.y)) * ci + u.y;
        float sq = t0*t0 + t1*t1;
        #pragma unroll
        for (int off = 16; off; off >>= 1) sq += __shfl_xor_sync(0xffffffffu, sq, off);
        float inv = 1.f / (sqrtf(sq) + 1e-12f);
        float2 s2 = ((const float2*)(g_S + base))[lane];
        float hp0 = t0 * inv + s2.x;
        float hp1 = t1 * inv + s2.y;
        ((float2*)(g_hpre + base))[lane] = make_float2(hp0, hp1);
        cs0 += hp0; css0 += hp0*hp0;
        cs1 += hp1; css1 += hp1*hp1;
    }
    // channel of cs0 = 2*lane, cs1 = 2*lane+1
    sRed[warp*128 + 2*lane]          = cs0;
    sRed[warp*128 + 2*lane + 1]      = cs1;
    sRed[warp*128 + 64 + 2*lane]     = css0;
    sRed[warp*128 + 64 + 2*lane + 1] = css1;
    __syncthreads();
    if (tid < 128) {
        float s = 0.f;
        #pragma unroll
        for (int w = 0; w < 8; w++) s += sRed[w*128 + tid];
        g_part[(size_t)blockIdx.x * 128 + tid] = s;
    }
}

// ---------------- BN finalize: reduce g_part -> g_bn ----------------
__global__ void __launch_bounds__(1024) k_bnfin(
    const float* __restrict__ gamma, const float* __restrict__ beta)
{
    __shared__ float sAcc[1024];
    int tid = threadIdx.x;
    int c = tid & 127, grp = tid >> 7;   // 8 groups
    float s = 0.f;
    for (int b = grp; b < GB; b += 8) s += g_part[(size_t)b * 128 + c];
    sAcc[grp * 128 + c] = s;
    __syncthreads();
    if (tid < 128) {
        float t = 0.f;
        #pragma unroll
        for (int g = 0; g < 8; g++) t += sAcc[g*128 + tid];
        sAcc[tid] = t;
    }
    __syncthreads();
    if (tid < 64) {
        float mu  = sAcc[tid] / (float)NN;
        float var = sAcc[64 + tid] / (float)NN - mu * mu;
        float rs  = 1.f / sqrtf(var + 1e-5f);
        float sc  = rs * gamma[tid];
        g_bn[tid] = sc;
        g_bn[64 + tid] = beta[tid] - mu * sc;
    }
}

// 16-slot butterfly multi-reduce: lane ends with full sum for code CODE(lane)
#define XSTEP(OFF, HALF) { \
    bool hi_ = (lane & OFF) != 0; \
    _Pragma("unroll") \
    for (int i_ = 0; i_ < HALF; i_++) { \
        float send_ = hi_ ? p[i_] : p[i_ + HALF]; \
        float recv_ = __shfl_xor_sync(0xffffffffu, send_, OFF); \
        p[i_] = (hi_ ? p[i_ + HALF] : p[i_]) + recv_; \
    } }
#define REDUCE16() XSTEP(1,8) XSTEP(2,4) XSTEP(4,2) XSTEP(8,1) \
    p[0] += __shfl_xor_sync(0xffffffffu, p[0], 16);

// ---------------- fused: BN apply + relu + xlocal + residual-VQ (+gnn head) --------
__global__ void __launch_bounds__(256) k_nodeB(
    const float* __restrict__ cbl, int layer,
    const float* __restrict__ Wg, const float* __restrict__ bg,
    float* __restrict__ out)
{
    __shared__ float sCb[48 * 65];
    __shared__ float sWg[16 * 65];
    __shared__ float sBn[128];
    __shared__ float sLoss[8];
    int tid = threadIdx.x, warp = tid >> 5, lane = tid & 31;
    if (tid < 128) sBn[tid] = g_bn[tid];
    for (int rid = warp; rid < 48; rid += 8) {
        float v0 = cbl[rid*64 + lane], v1 = cbl[rid*64 + lane + 32];
        float sq = v0*v0 + v1*v1;
        #pragma unroll
        for (int off = 16; off; off >>= 1) sq += __shfl_xor_sync(0xffffffffu, sq, off);
        float inv = 1.f / (sqrtf(sq) + 1e-12f);
        sCb[rid*65 + lane]      = v0 * inv;
        sCb[rid*65 + lane + 32] = v1 * inv;
    }
    for (int i = tid; i < 16*65; i += 256) sWg[i] = 0.f;
    __syncthreads();
    if (layer == 2) {
        for (int i = tid; i < 9*64; i += 256) {
            int j = i / 64, c = i - j*64;
            sWg[j*65 + c] = Wg[c*9 + j];   // transpose [64,9] -> [9,64]
        }
    }
    __syncthreads();

    int mycode = ((lane&1)<<3) | ((lane&2)<<1) | ((lane&4)>>1) | ((lane&8)>>3);
    float lossAcc = 0.f;
    int stride = gridDim.x * 8;
    for (int n = blockIdx.x * 8 + warp; n < NN; n += stride) {
        size_t base = (size_t)n * 64;
        float hp0 = g_hpre[base + lane], hp1 = g_hpre[base + lane + 32];
        float h0 = fmaxf(0.f, fmaf(hp0, sBn[lane],      sBn[64 + lane]));
        float h1 = fmaxf(0.f, fmaf(hp1, sBn[lane + 32], sBn[96 + lane]));
        float xl0 = h0, xl1 = h1;
        if (layer) {
            xl0 += g_xlocal[base + lane];
            xl1 += g_xlocal[base + lane + 32];
        }
        g_xlocal[base + lane] = xl0;
        g_xlocal[base + lane + 32] = xl1;
        if (layer != 2) {
            g_h[base + lane] = h0;
            g_h[base + lane + 32] = h1;
        }
        float r0 = h0, r1 = h1;
        #pragma unroll
        for (int r = 0; r < 3; r++) {
            float p[16];
            #pragma unroll
            for (int j = 0; j < 16; j++) {
                const float* cb = &sCb[(r*16 + j) * 65];
                p[j] = r0 * cb[lane] + r1 * cb[lane + 32];
            }
            REDUCE16();
            float bs = p[0]; int best = mycode;
            #pragma unroll
            for (int off = 8; off; off >>= 1) {
                float os = __shfl_xor_sync(0xffffffffu, bs, off);
                int   oc = __shfl_xor_sync(0xffffffffu, best, off);
                if (os > bs || (os == bs && oc < best)) { bs = os; best = oc; }
            }
            const float* cq = &sCb[(r*16 + best) * 65];
            float q0 = cq[lane], q1 = cq[lane + 32];
            float d0 = q0 - r0, d1 = q1 - r1;
            lossAcc += d0*d0 + d1*d1;
            r0 -= q0; r1 -= q1;
            if (lane == 0) out[IDS_OFF + (size_t)n*9 + layer*3 + r] = (float)best;
        }
        if (layer == 2) {
            float p[16];
            #pragma unroll
            for (int j = 0; j < 16; j++) {
                const float* wrow = &sWg[j * 65];
                p[j] = xl0 * wrow[lane] + xl1 * wrow[lane + 32];
            }
            REDUCE16();
            if (lane < 16 && mycode < 9)
                out[GNN_OFF + (size_t)n*9 + mycode] = p[0] + bg[mycode];
        }
    }
    #pragma unroll
    for (int off = 16; off; off >>= 1) lossAcc += __shfl_xor_sync(0xffffffffu, lossAcc, off);
    if (lane == 0) sLoss[warp] = lossAcc;
    __syncthreads();
    if (tid == 0) {
        float s = 0.f;
        #pragma unroll
        for (int w = 0; w < 8; w++) s += sLoss[w];
        g_cpart[layer * NODEB_BLOCKS + blockIdx.x] = s;
    }
}

// ---------------- pred head: xlocal @ Wp + bp (packed GEMM) + commit + state reset --
#define LDT 72
__global__ void __launch_bounds__(256) k_pred(
    const float* __restrict__ Wp, const float* __restrict__ bp,
    float* __restrict__ out)
{
    __shared__ __align__(16) float sW[4096];
    __shared__ __align__(16) float sX[64 * LDT];
    int tid = threadIdx.x;
    int node0 = blockIdx.x * 64;

    // restore the zero-state invariant for the next replay
    {
        int gi = blockIdx.x * 256 + tid;
        if (gi < NN) { g_deg[gi] = 0; g_fill[gi] = 0; }
    }

    for (int i = tid; i < 1024; i += 256) ((float4*)sW)[i] = ((const float4*)Wp)[i];
    for (int i = tid; i < 1024; i += 256) {
        int n = i >> 4, kc = i & 15;
        int node = node0 + n;
        float4 v = make_float4(0.f, 0.f, 0.f, 0.f);
        if (node < NN) v = *(const float4*)(g_xlocal + (size_t)node*64 + kc*4);
        int kb = kc * 4;
        sX[(kb+0)*LDT+n] = v.x; sX[(kb+1)*LDT+n] = v.y;
        sX[(kb+2)*LDT+n] = v.z; sX[(kb+3)*LDT+n] = v.w;
    }
    __syncthreads();
    int tx = tid & 15, ty = tid >> 4, c0 = tx*4, n0 = ty*4;
    unsigned long long acc2[4][2];
    {
        float4 bb = *(const float4*)(bp + c0);
        #pragma unroll
        for (int i2 = 0; i2 < 4; i2++) {
            acc2[i2][0] = pk2(bb.x, bb.y);
            acc2[i2][1] = pk2(bb.z, bb.w);
        }
    }
    #pragma unroll 4
    for (int k = 0; k < 64; k++) {
        float2 a01 = *(const float2*)&sX[k*LDT + n0];
        float2 a23 = *(const float2*)&sX[k*LDT + n0 + 2];
        unsigned long long p0 = pk2(a01.x, a01.x);
        unsigned long long p1 = pk2(a01.y, a01.y);
        unsigned long long p2 = pk2(a23.x, a23.x);
        unsigned long long p3 = pk2(a23.y, a23.y);
        ulonglong2 w = *(const ulonglong2*)&sW[k*64 + c0];
        fma2(acc2[0][0], p0, w.x); fma2(acc2[0][1], p0, w.y);
        fma2(acc2[1][0], p1, w.x); fma2(acc2[1][1], p1, w.y);
        fma2(acc2[2][0], p2, w.x); fma2(acc2[2][1], p2, w.y);
        fma2(acc2[3][0], p3, w.x); fma2(acc2[3][1], p3, w.y);
    }
    #pragma unroll
    for (int i2 = 0; i2 < 4; i2++) {
        int node = node0 + n0 + i2;
        if (node < NN) {
            float2 lo = upk2(acc2[i2][0]);
            float2 hi = upk2(acc2[i2][1]);
            float4 o = make_float4(lo.x, lo.y, hi.x, hi.y);
            *(float4*)(out + (size_t)node*64 + c0) = o;
        }
    }
    if (blockIdx.x == 0) {
        int lane = tid & 31;
        if (tid < 32) {
            float s = 0.f;
            for (int i = lane; i < 3 * NODEB_BLOCKS; i += 32) s += g_cpart[i];
            #pragma unroll
            for (int off = 16; off; off >>= 1) s += __shfl_xor_sync(0xffffffffu, s, off);
            if (lane == 0) out[COMMIT_OFF] = s * (0.25f / (float)(NN * 64));
        }
    }
}

// ---------------- launch ----------------
extern "C" void kernel_launch(void* const* d_in, const int* in_sizes, int n_in,
                              void* d_out, int out_size) {
    const float* x       = (const float*)d_in[0];
    const void*  eiv     = d_in[1];
    const float* Wa      = (const float*)d_in[2];
    const float* ba      = (const float*)d_in[3];
    const float* Wr      = (const float*)d_in[4];
    const float* Wl      = (const float*)d_in[5];
    const float* bl      = (const float*)d_in[6];
    const float* gamma   = (const float*)d_in[7];
    const float* beta    = (const float*)d_in[8];
    const float* cbs     = (const float*)d_in[9];
    const float* Wp      = (const float*)d_in[10];
    const float* bp      = (const float*)d_in[11];
    const float* Wg      = (const float*)d_in[12];
    const float* bg      = (const float*)d_in[13];
    float* out = (float*)d_out;

    cudaFuncSetAttribute(k_gemm3, cudaFuncAttributeMaxDynamicSharedMemorySize,
                         GEMM3_SMEM);

    k_prep<<<(NE + 255)/256, 256>>>(eiv);
    k_scanA<<<SCANB, 1024>>>();
    k_fill<<<(NE + 255)/256, 256>>>(eiv);

    for (int i = 0; i < 3; i++) {
        k_gemm3<<<GEMM_GRID, 256, GEMM3_SMEM>>>(x, i,
            Wa + i*4096, Wr + i*4096, Wl + i*4096, ba + i*64, bl + i*64);
        k_gath2<<<GB, 256>>>();
        k_bnfin<<<1, 1024>>>(gamma + i*64, beta + i*64);
        k_nodeB<<<NODEB_BLOCKS, 256>>>(cbs + i*3*16*64, i, Wg, bg, out);
    }
    k_pred<<<(NN + 63)/64, 256>>>(Wp, bp, out);
}

// round 16
// speedup vs baseline: 1.0857x; 1.0857x over previous
#include <cuda_runtime.h>

#define NN 100000
#define NE 1000000

#define GB ((NN + 63) / 64)               // 1563 tiles
#define NODEB_BLOCKS 1480
#define SCANB ((NN + 1023) / 1024)        // 98

#define COMMIT_OFF (NN*64)
#define IDS_OFF (COMMIT_OFF+1)
#define GNN_OFF (IDS_OFF + NN*9)

// ---------------- packed f32x2 helpers ----------------
__device__ __forceinline__ unsigned long long pk2(float lo, float hi) {
    unsigned long long r;
    asm("mov.b64 %0, {%1,%2};" : "=l"(r) : "f"(lo), "f"(hi));
    return r;
}
__device__ __forceinline__ float2 upk2(unsigned long long v) {
    float2 f;
    asm("mov.b64 {%0,%1}, %2;" : "=f"(f.x), "=f"(f.y) : "l"(v));
    return f;
}
__device__ __forceinline__ void fma2(unsigned long long& d,
                                     unsigned long long a, unsigned long long b) {
    asm("fma.rn.f32x2 %0, %1, %2, %0;" : "+l"(d) : "l"(a), "l"(b));
}

// ---------------- scratch (__device__ globals; zero-initialized at load) ----------
// INVARIANT: g_deg, g_fill are zero at the start of every kernel_launch sequence
// (module-load zeros the first run; k_pred re-zeroes them at the end of each run).
__device__ __align__(16) float g_h[NN*64];
__device__ __align__(16) float g_hpre[NN*64];
__device__ __align__(16) float g_xlocal[NN*64];
__device__ __align__(16) float g_Y[NN*64];   // h@Wa
__device__ __align__(16) float g_U[NN*64];   // h@Wr + ba
__device__ __align__(16) float g_S[NN*64];   // h@Wl + bl
__device__ int   g_csr[NE];
__device__ int   g_deg[NN];
__device__ int   g_fill[NN];
__device__ int   g_rowstart[NN];              // local-exclusive
__device__ int   g_rowabs[NN];                // absolute CSR row start
__device__ int   g_bsum[SCANB];
__device__ float g_part[GB * 128];            // per-block BN partials
__device__ float g_cpart[3 * NODEB_BLOCKS];   // per-block commit partials
__device__ float g_bn[128];                   // [0:64) scale, [64:128) shift

// per-warp dtype detect: int64 values < 2^31 have zero hi-words
__device__ __forceinline__ bool warp_is64(const int* ei32, int e) {
    int eC = (e < NE) ? e : NE - 1;
    int hi = ei32[2*eC + 1];
    return __ballot_sync(0xffffffffu, hi != 0) == 0u;
}

// ---------------- degree count ----------------
__global__ void k_prep(const void* __restrict__ eiv) {
    int e = blockIdx.x * blockDim.x + threadIdx.x;
    bool is64 = warp_is64((const int*)eiv, e);
    if (e < NE) {
        int d = is64 ? (int)((const long long*)eiv)[NE + e]
                     : ((const int*)eiv)[NE + e];
        atomicAdd(&g_deg[d], 1);
    }
}

// per-block Hillis-Steele scan of 1024 degrees; local exclusive -> rowstart
__global__ void __launch_bounds__(1024) k_scanA() {
    __shared__ int ss[1024];
    int t = threadIdx.x;
    int node = blockIdx.x * 1024 + t;
    int d = (node < NN) ? g_deg[node] : 0;
    ss[t] = d;
    __syncthreads();
    #pragma unroll
    for (int off = 1; off < 1024; off <<= 1) {
        int v = (t >= off) ? ss[t - off] : 0;
        __syncthreads();
        ss[t] += v;
        __syncthreads();
    }
    if (node < NN) g_rowstart[node] = ss[t] - d;
    if (t == 1023) g_bsum[blockIdx.x] = ss[1023];
}

// helper: redundant in-block scan of the 98 block sums -> sB (inclusive)
__device__ __forceinline__ void scan_bsum(int* sB, int tid) {
    if (tid < 128) sB[tid] = (tid < SCANB) ? g_bsum[tid] : 0;
    __syncthreads();
    #pragma unroll
    for (int off = 1; off < 128; off <<= 1) {
        int v = 0;
        if (tid < 128 && tid >= off) v = sB[tid - off];
        __syncthreads();
        if (tid < 128) sB[tid] += v;
        __syncthreads();
    }
}

// counting-sort edges into CSR + write absolute row starts
__global__ void k_fill(const void* __restrict__ eiv) {
    __shared__ int sB[128];
    int t = threadIdx.x;
    scan_bsum(sB, t);
    int e = blockIdx.x * blockDim.x + t;
    if (e < NN) {
        int blk = e >> 10;
        g_rowabs[e] = g_rowstart[e] + (blk ? sB[blk - 1] : 0);
    }
    bool is64 = warp_is64((const int*)eiv, e);
    if (e < NE) {
        int s, d;
        if (is64) {
            s = (int)((const long long*)eiv)[e];
            d = (int)((const long long*)eiv)[NE + e];
        } else {
            s = ((const int*)eiv)[e];
            d = ((const int*)eiv)[NE + e];
        }
        int blk = d >> 10;
        int pos = g_rowstart[d] + (blk ? sB[blk - 1] : 0) + atomicAdd(&g_fill[d], 1);
        g_csr[pos] = s;
    }
}

// ---------------- dense single-pass GEMM: [Y|U|S] = h @ [Wa|Wr|Wl] + [0|ba|bl] ----
// (per-tile grid: best measured structure, R14)
#define SST 66
#define GEMM3_SMEM ((64*SST + 3*4096) * 4)   // 66048 bytes
__global__ void __launch_bounds__(256) k_gemm3(
    const float* __restrict__ x, int layer,
    const float* __restrict__ Wa, const float* __restrict__ Wr,
    const float* __restrict__ Wl,
    const float* __restrict__ ba, const float* __restrict__ bl)
{
    const float* __restrict__ hin = layer ? g_h : x;
    extern __shared__ __align__(16) float dyn[];
    float* sT = dyn;                 // [k][n] stride 66
    float* sW = dyn + 64 * SST;      // Wa | Wr | Wl

    int tid = threadIdx.x;
    int node0 = blockIdx.x * 64;

    for (int i = tid; i < 1024; i += 256) {
        int n = i >> 4, kc = i & 15;
        int node = node0 + n;
        float4 hv = make_float4(0.f, 0.f, 0.f, 0.f);
        if (node < NN) hv = *(const float4*)(hin + (size_t)node * 64 + kc * 4);
        int kb = kc * 4;
        sT[(kb+0)*SST+n] = hv.x; sT[(kb+1)*SST+n] = hv.y;
        sT[(kb+2)*SST+n] = hv.z; sT[(kb+3)*SST+n] = hv.w;
    }
    for (int i = tid; i < 3072; i += 256) {
        const float* src = (i < 1024) ? Wa : (i < 2048) ? Wr : Wl;
        ((float4*)sW)[i] = ((const float4*)src)[i & 1023];
    }
    __syncthreads();

    int tx = tid & 15, ty = tid >> 4;
    int c0 = tx * 4, n0 = ty * 4;
    unsigned long long aY[4][2], aU[4][2], aS[4][2];
    {
        float4 bu = *(const float4*)(ba + c0);
        float4 bs = *(const float4*)(bl + c0);
        #pragma unroll
        for (int i2 = 0; i2 < 4; i2++) {
            aY[i2][0] = pk2(0.f, 0.f);   aY[i2][1] = pk2(0.f, 0.f);
            aU[i2][0] = pk2(bu.x, bu.y); aU[i2][1] = pk2(bu.z, bu.w);
            aS[i2][0] = pk2(bs.x, bs.y); aS[i2][1] = pk2(bs.z, bs.w);
        }
    }

    #pragma unroll 4
    for (int k = 0; k < 64; k++) {
        float2 a01 = *(const float2*)&sT[k*SST + n0];
        float2 a23 = *(const float2*)&sT[k*SST + n0 + 2];
        unsigned long long p0 = pk2(a01.x, a01.x);
        unsigned long long p1 = pk2(a01.y, a01.y);
        unsigned long long p2 = pk2(a23.x, a23.x);
        unsigned long long p3 = pk2(a23.y, a23.y);
        ulonglong2 wa = *(const ulonglong2*)&sW[k*64 + c0];
        ulonglong2 wr = *(const ulonglong2*)&sW[4096 + k*64 + c0];
        ulonglong2 wl = *(const ulonglong2*)&sW[8192 + k*64 + c0];
        fma2(aY[0][0], p0, wa.x); fma2(aY[0][1], p0, wa.y);
        fma2(aY[1][0], p1, wa.x); fma2(aY[1][1], p1, wa.y);
        fma2(aY[2][0], p2, wa.x); fma2(aY[2][1], p2, wa.y);
        fma2(aY[3][0], p3, wa.x); fma2(aY[3][1], p3, wa.y);
        fma2(aU[0][0], p0, wr.x); fma2(aU[0][1], p0, wr.y);
        fma2(aU[1][0], p1, wr.x); fma2(aU[1][1], p1, wr.y);
        fma2(aU[2][0], p2, wr.x); fma2(aU[2][1], p2, wr.y);
        fma2(aU[3][0], p3, wr.x); fma2(aU[3][1], p3, wr.y);
        fma2(aS[0][0], p0, wl.x); fma2(aS[0][1], p0, wl.y);
        fma2(aS[1][0], p1, wl.x); fma2(aS[1][1], p1, wl.y);
        fma2(aS[2][0], p2, wl.x); fma2(aS[2][1], p2, wl.y);
        fma2(aS[3][0], p3, wl.x); fma2(aS[3][1], p3, wl.y);
    }

    #pragma unroll
    for (int i2 = 0; i2 < 4; i2++) {
        int node = node0 + n0 + i2;
        if (node < NN) {
            size_t b = (size_t)node * 64 + c0;
            float2 lo, hi;
            lo = upk2(aY[i2][0]); hi = upk2(aY[i2][1]);
            *(float4*)(g_Y + b) = make_float4(lo.x, lo.y, hi.x, hi.y);
            lo = upk2(aU[i2][0]); hi = upk2(aU[i2][1]);
            *(float4*)(g_U + b) = make_float4(lo.x, lo.y, hi.x, hi.y);
            lo = upk2(aS[i2][0]); hi = upk2(aS[i2][1]);
            *(float4*)(g_S + b) = make_float4(lo.x, lo.y, hi.x, hi.y);
        }
    }
}

// ---------------- gather + l2norm + skip: hpre = l2n(mean(Y[src]) + U) + S -------
// lane handles channels (2*lane, 2*lane+1)
__global__ void __launch_bounds__(256) k_gath2() {
    __shared__ float sRed[8 * 128];
    int tid = threadIdx.x, warp = tid >> 5, lane = tid & 31;

    int node0 = blockIdx.x * 64;
    float cs0 = 0.f, css0 = 0.f, cs1 = 0.f, css1 = 0.f;
    for (int r = warp * 8; r < warp * 8 + 8; r++) {
        int node = node0 + r;
        if (node >= NN) continue;     // warp-uniform
        int beg = g_rowabs[node];
        int dg  = g_deg[node];
        int end = beg + dg;
        float2 a = make_float2(0.f, 0.f), b = a, c = a, d = a;
        int j = beg;
        for (; j + 3 < end; j += 4) {
            float2 v0 = ((const float2*)(g_Y + (size_t)g_csr[j]     * 64))[lane];
            float2 v1 = ((const float2*)(g_Y + (size_t)g_csr[j + 1] * 64))[lane];
            float2 v2 = ((const float2*)(g_Y + (size_t)g_csr[j + 2] * 64))[lane];
            float2 v3 = ((const float2*)(g_Y + (size_t)g_csr[j + 3] * 64))[lane];
            a.x += v0.x; a.y += v0.y;
            b.x += v1.x; b.y += v1.y;
            c.x += v2.x; c.y += v2.y;
            d.x += v3.x; d.y += v3.y;
        }
        for (; j < end; j++) {
            float2 v0 = ((const float2*)(g_Y + (size_t)g_csr[j] * 64))[lane];
            a.x += v0.x; a.y += v0.y;
        }
        float ci = 1.f / (float)(dg > 0 ? dg : 1);
        size_t base = (size_t)node * 64;
        float2 u = ((const float2*)(g_U + base))[lane];
        float t0 = ((a.x + b.x) + (c.x + d.x)) * ci + u.x;
        float t1 = ((a.y + b.y) + (c.y + d.y)) * ci + u.y;
        float sq = t0*t0 + t1*t1;
        #pragma unroll
        for (int off = 16; off; off >>= 1) sq += __shfl_xor_sync(0xffffffffu, sq, off);
        float inv = 1.f / (sqrtf(sq) + 1e-12f);
        float2 s2 = ((const float2*)(g_S + base))[lane];
        float hp0 = t0 * inv + s2.x;
        float hp1 = t1 * inv + s2.y;
        ((float2*)(g_hpre + base))[lane] = make_float2(hp0, hp1);
        cs0 += hp0; css0 += hp0*hp0;
        cs1 += hp1; css1 += hp1*hp1;
    }
    sRed[warp*128 + 2*lane]          = cs0;
    sRed[warp*128 + 2*lane + 1]      = cs1;
    sRed[warp*128 + 64 + 2*lane]     = css0;
    sRed[warp*128 + 64 + 2*lane + 1] = css1;
    __syncthreads();
    if (tid < 128) {
        float s = 0.f;
        #pragma unroll
        for (int w = 0; w < 8; w++) s += sRed[w*128 + tid];
        g_part[(size_t)blockIdx.x * 128 + tid] = s;
    }
}

// ---------------- BN finalize: reduce g_part -> g_bn ----------------
__global__ void __launch_bounds__(1024) k_bnfin(
    const float* __restrict__ gamma, const float* __restrict__ beta)
{
    __shared__ float sAcc[1024];
    int tid = threadIdx.x;
    int c = tid & 127, grp = tid >> 7;   // 8 groups
    float s = 0.f;
    for (int b = grp; b < GB; b += 8) s += g_part[(size_t)b * 128 + c];
    sAcc[grp * 128 + c] = s;
    __syncthreads();
    if (tid < 128) {
        float t = 0.f;
        #pragma unroll
        for (int g = 0; g < 8; g++) t += sAcc[g*128 + tid];
        sAcc[tid] = t;
    }
    __syncthreads();
    if (tid < 64) {
        float mu  = sAcc[tid] / (float)NN;
        float var = sAcc[64 + tid] / (float)NN - mu * mu;
        float rs  = 1.f / sqrtf(var + 1e-5f);
        float sc  = rs * gamma[tid];
        g_bn[tid] = sc;
        g_bn[64 + tid] = beta[tid] - mu * sc;
    }
}

// 16-slot butterfly multi-reduce: lane ends with full sum for code CODE(lane)
#define XSTEP(OFF, HALF) { \
    bool hi_ = (lane & OFF) != 0; \
    _Pragma("unroll") \
    for (int i_ = 0; i_ < HALF; i_++) { \
        float send_ = hi_ ? p[i_] : p[i_ + HALF]; \
        float recv_ = __shfl_xor_sync(0xffffffffu, send_, OFF); \
        p[i_] = (hi_ ? p[i_ + HALF] : p[i_]) + recv_; \
    } }
#define REDUCE16() XSTEP(1,8) XSTEP(2,4) XSTEP(4,2) XSTEP(8,1) \
    p[0] += __shfl_xor_sync(0xffffffffu, p[0], 16);

// ---------------- fused: BN apply + relu + xlocal + residual-VQ (+gnn head) --------
// lane handles channels (2*lane, 2*lane+1); sCb/sWg stride 66 for aligned LDS.64
__global__ void __launch_bounds__(256) k_nodeB(
    const float* __restrict__ cbl, int layer,
    const float* __restrict__ Wg, const float* __restrict__ bg,
    float* __restrict__ out)
{
    __shared__ __align__(16) float sCb[48 * 66];
    __shared__ __align__(16) float sWg[16 * 66];
    __shared__ __align__(16) float sBn[128];
    __shared__ float sLoss[8];
    int tid = threadIdx.x, warp = tid >> 5, lane = tid & 31;
    if (tid < 128) sBn[tid] = g_bn[tid];
    for (int rid = warp; rid < 48; rid += 8) {
        float v0 = cbl[rid*64 + lane], v1 = cbl[rid*64 + lane + 32];
        float sq = v0*v0 + v1*v1;
        #pragma unroll
        for (int off = 16; off; off >>= 1) sq += __shfl_xor_sync(0xffffffffu, sq, off);
        float inv = 1.f / (sqrtf(sq) + 1e-12f);
        sCb[rid*66 + lane]      = v0 * inv;
        sCb[rid*66 + lane + 32] = v1 * inv;
    }
    for (int i = tid; i < 16*66; i += 256) sWg[i] = 0.f;
    __syncthreads();
    if (layer == 2) {
        for (int i = tid; i < 9*64; i += 256) {
            int j = i / 64, c = i - j*64;
            sWg[j*66 + c] = Wg[c*9 + j];   // transpose [64,9] -> [9,64]
        }
    }
    __syncthreads();

    int mycode = ((lane&1)<<3) | ((lane&2)<<1) | ((lane&4)>>1) | ((lane&8)>>3);
    float lossAcc = 0.f;
    int stride = gridDim.x * 8;
    for (int n = blockIdx.x * 8 + warp; n < NN; n += stride) {
        size_t base = (size_t)n * 64;
        float2 hp = ((const float2*)(g_hpre + base))[lane];
        float2 sc = ((const float2*)sBn)[lane];          // scales for c0,c1
        float2 sh = ((const float2*)(sBn + 64))[lane];   // shifts
        float h0 = fmaxf(0.f, fmaf(hp.x, sc.x, sh.x));
        float h1 = fmaxf(0.f, fmaf(hp.y, sc.y, sh.y));
        float xl0 = h0, xl1 = h1;
        if (layer) {
            float2 xl = ((const float2*)(g_xlocal + base))[lane];
            xl0 += xl.x; xl1 += xl.y;
        }
        ((float2*)(g_xlocal + base))[lane] = make_float2(xl0, xl1);
        if (layer != 2)
            ((float2*)(g_h + base))[lane] = make_float2(h0, h1);
        float r0 = h0, r1 = h1;
        #pragma unroll
        for (int r = 0; r < 3; r++) {
            float p[16];
            #pragma unroll
            for (int j = 0; j < 16; j++) {
                float2 cb2 = *(const float2*)&sCb[(r*16 + j) * 66 + 2*lane];
                p[j] = r0 * cb2.x + r1 * cb2.y;
            }
            REDUCE16();
            float bs = p[0]; int best = mycode;
            #pragma unroll
            for (int off = 8; off; off >>= 1) {
                float os = __shfl_xor_sync(0xffffffffu, bs, off);
                int   oc = __shfl_xor_sync(0xffffffffu, best, off);
                if (os > bs || (os == bs && oc < best)) { bs = os; best = oc; }
            }
            float2 cq2 = *(const float2*)&sCb[(r*16 + best) * 66 + 2*lane];
            float d0 = cq2.x - r0, d1 = cq2.y - r1;
            lossAcc += d0*d0 + d1*d1;
            r0 -= cq2.x; r1 -= cq2.y;
            if (lane == 0) out[IDS_OFF + (size_t)n*9 + layer*3 + r] = (float)best;
        }
        if (layer == 2) {
            float p[16];
            #pragma unroll
            for (int j = 0; j < 16; j++) {
                float2 w2 = *(const float2*)&sWg[j * 66 + 2*lane];
                p[j] = xl0 * w2.x + xl1 * w2.y;
            }
            REDUCE16();
            if (lane < 16 && mycode < 9)
                out[GNN_OFF + (size_t)n*9 + mycode] = p[0] + bg[mycode];
        }
    }
    #pragma unroll
    for (int off = 16; off; off >>= 1) lossAcc += __shfl_xor_sync(0xffffffffu, lossAcc, off);
    if (lane == 0) sLoss[warp] = lossAcc;
    __syncthreads();
    if (tid == 0) {
        float s = 0.f;
        #pragma unroll
        for (int w = 0; w < 8; w++) s += sLoss[w];
        g_cpart[layer * NODEB_BLOCKS + blockIdx.x] = s;
    }
}

// ---------------- pred head: xlocal @ Wp + bp (packed GEMM) + commit + state reset --
#define LDT 72
__global__ void __launch_bounds__(256) k_pred(
    const float* __restrict__ Wp, const float* __restrict__ bp,
    float* __restrict__ out)
{
    __shared__ __align__(16) float sW[4096];
    __shared__ __align__(16) float sX[64 * LDT];
    int tid = threadIdx.x;
    int node0 = blockIdx.x * 64;

    // restore the zero-state invariant for the next replay
    {
        int gi = blockIdx.x * 256 + tid;
        if (gi < NN) { g_deg[gi] = 0; g_fill[gi] = 0; }
    }

    for (int i = tid; i < 1024; i += 256) ((float4*)sW)[i] = ((const float4*)Wp)[i];
    for (int i = tid; i < 1024; i += 256) {
        int n = i >> 4, kc = i & 15;
        int node = node0 + n;
        float4 v = make_float4(0.f, 0.f, 0.f, 0.f);
        if (node < NN) v = *(const float4*)(g_xlocal + (size_t)node*64 + kc*4);
        int kb = kc * 4;
        sX[(kb+0)*LDT+n] = v.x; sX[(kb+1)*LDT+n] = v.y;
        sX[(kb+2)*LDT+n] = v.z; sX[(kb+3)*LDT+n] = v.w;
    }
    __syncthreads();
    int tx = tid & 15, ty = tid >> 4, c0 = tx*4, n0 = ty*4;
    unsigned long long acc2[4][2];
    {
        float4 bb = *(const float4*)(bp + c0);
        #pragma unroll
        for (int i2 = 0; i2 < 4; i2++) {
            acc2[i2][0] = pk2(bb.x, bb.y);
            acc2[i2][1] = pk2(bb.z, bb.w);
        }
    }
    #pragma unroll 4
    for (int k = 0; k < 64; k++) {
        float2 a01 = *(const float2*)&sX[k*LDT + n0];
        float2 a23 = *(const float2*)&sX[k*LDT + n0 + 2];
        unsigned long long p0 = pk2(a01.x, a01.x);
        unsigned long long p1 = pk2(a01.y, a01.y);
        unsigned long long p2 = pk2(a23.x, a23.x);
        unsigned long long p3 = pk2(a23.y, a23.y);
        ulonglong2 w = *(const ulonglong2*)&sW[k*64 + c0];
        fma2(acc2[0][0], p0, w.x); fma2(acc2[0][1], p0, w.y);
        fma2(acc2[1][0], p1, w.x); fma2(acc2[1][1], p1, w.y);
        fma2(acc2[2][0], p2, w.x); fma2(acc2[2][1], p2, w.y);
        fma2(acc2[3][0], p3, w.x); fma2(acc2[3][1], p3, w.y);
    }
    #pragma unroll
    for (int i2 = 0; i2 < 4; i2++) {
        int node = node0 + n0 + i2;
        if (node < NN) {
            float2 lo = upk2(acc2[i2][0]);
            float2 hi = upk2(acc2[i2][1]);
            float4 o = make_float4(lo.x, lo.y, hi.x, hi.y);
            *(float4*)(out + (size_t)node*64 + c0) = o;
        }
    }
    if (blockIdx.x == 0) {
        int lane = tid & 31;
        if (tid < 32) {
            float s = 0.f;
            for (int i = lane; i < 3 * NODEB_BLOCKS; i += 32) s += g_cpart[i];
            #pragma unroll
            for (int off = 16; off; off >>= 1) s += __shfl_xor_sync(0xffffffffu, s, off);
            if (lane == 0) out[COMMIT_OFF] = s * (0.25f / (float)(NN * 64));
        }
    }
}

// ---------------- launch ----------------
extern "C" void kernel_launch(void* const* d_in, const int* in_sizes, int n_in,
                              void* d_out, int out_size) {
    const float* x       = (const float*)d_in[0];
    const void*  eiv     = d_in[1];
    const float* Wa      = (const float*)d_in[2];
    const float* ba      = (const float*)d_in[3];
    const float* Wr      = (const float*)d_in[4];
    const float* Wl      = (const float*)d_in[5];
    const float* bl      = (const float*)d_in[6];
    const float* gamma   = (const float*)d_in[7];
    const float* beta    = (const float*)d_in[8];
    const float* cbs     = (const float*)d_in[9];
    const float* Wp      = (const float*)d_in[10];
    const float* bp      = (const float*)d_in[11];
    const float* Wg      = (const float*)d_in[12];
    const float* bg      = (const float*)d_in[13];
    float* out = (float*)d_out;

    // one-time stream/event creation on the first (non-captured) call
    static bool s_init = false;
    static cudaStream_t sB;
    static cudaEvent_t evF, evJ;
    if (!s_init) {
        cudaStreamCreateWithFlags(&sB, cudaStreamNonBlocking);
        cudaEventCreateWithFlags(&evF, cudaEventDisableTiming);
        cudaEventCreateWithFlags(&evJ, cudaEventDisableTiming);
        s_init = true;
    }

    cudaFuncSetAttribute(k_gemm3, cudaFuncAttributeMaxDynamicSharedMemorySize,
                         GEMM3_SMEM);

    // fork: layer-0 dense GEMM (depends only on x) overlaps the CSR build
    cudaEventRecord(evF, 0);
    cudaStreamWaitEvent(sB, evF, 0);
    k_gemm3<<<GB, 256, GEMM3_SMEM, sB>>>(x, 0,
        Wa, Wr, Wl, ba, bl);
    cudaEventRecord(evJ, sB);

    k_prep<<<(NE + 255)/256, 256>>>(eiv);
    k_scanA<<<SCANB, 1024>>>();
    k_fill<<<(NE + 255)/256, 256>>>(eiv);

    // join: gather needs both CSR (legacy) and Y/U/S (sB)
    cudaStreamWaitEvent(0, evJ, 0);

    for (int i = 0; i < 3; i++) {
        if (i)
            k_gemm3<<<GB, 256, GEMM3_SMEM>>>(x, i,
                Wa + i*4096, Wr + i*4096, Wl + i*4096, ba + i*64, bl + i*64);
        k_gath2<<<GB, 256>>>();
        k_bnfin<<<1, 1024>>>(gamma + i*64, beta + i*64);
        k_nodeB<<<NODEB_BLOCKS, 256>>>(cbs + i*3*16*64, i, Wg, bg, out);
    }
    k_pred<<<(NN + 63)/64, 256>>>(Wp, bp, out);
}